// round 9
// baseline (speedup 1.0000x reference)
#include <cuda_runtime.h>
#include <cuda_bf16.h>
#include <cstdint>

#define N_VAR 4194304
#define M_CHK 2097152
#define DC 10
#define CBLK 256
#define TILE_INTS (CBLK * DC)          // 2560 ints per tile
#define TILE_BYTES (TILE_INTS * 4)     // 10240 B per tile
#define NBLOCKS (M_CHK / (2 * CBLK))   // 4096 blocks, 2 tiles each

// scratch (device globals: allocation-free)
__device__ float g_b0[N_VAR];
__device__ float g_b1[N_VAR];
__device__ float g_b2[N_VAR];

__device__ __forceinline__ uint32_t smem_u32(const void* p) {
    uint32_t a;
    asm("{ .reg .u64 t; cvta.to.shared.u64 t, %1; cvt.u32.u64 %0, t; }" : "=r"(a) : "l"(p));
    return a;
}

__device__ __forceinline__ void mbar_init(uint32_t mbar, uint32_t cnt) {
    asm volatile("mbarrier.init.shared.b64 [%0], %1;" :: "r"(mbar), "r"(cnt) : "memory");
}
__device__ __forceinline__ void tma_1d(uint32_t sdst, const void* gsrc, uint32_t bytes,
                                       uint32_t mbar) {
    asm volatile("mbarrier.arrive.expect_tx.shared.b64 _, [%0], %1;"
                 :: "r"(mbar), "r"(bytes) : "memory");
    asm volatile(
        "cp.async.bulk.shared::cta.global.mbarrier::complete_tx::bytes [%0], [%1], %2, [%3];"
        :: "r"(sdst), "l"(gsrc), "r"(bytes), "r"(mbar) : "memory");
}
__device__ __forceinline__ void mbar_wait0(uint32_t mbar) {
    uint32_t done;
    asm volatile(
        "{\n\t.reg .pred p;\n\t"
        "mbarrier.try_wait.parity.acquire.cta.shared::cta.b64 p, [%1], 0;\n\t"
        "selp.b32 %0, 1, 0, p;\n\t}"
        : "=r"(done) : "r"(mbar) : "memory");
    while (!done) {
        asm volatile(
            "{\n\t.reg .pred p;\n\t"
            "mbarrier.try_wait.parity.acquire.cta.shared::cta.b64 p, [%1], 0, 0x989680;\n\t"
            "selp.b32 %0, 1, 0, p;\n\t}"
            : "=r"(done) : "r"(mbar) : "memory");
    }
}

// seed accumulator: acc = scale*llr0 - v2c_prev  (scale = 1 mid, 2 for final/out)
__global__ void __launch_bounds__(512) bp_seed(const float* __restrict__ llr0,
                                               const float* __restrict__ v2c_prev,
                                               float* __restrict__ acc, float scale) {
    int i = blockIdx.x * 512 + threadIdx.x;
    float4 l = __ldg(&reinterpret_cast<const float4*>(llr0)[i]);
    float4 p = __ldg(&reinterpret_cast<const float4*>(v2c_prev)[i]);
    float4 s = make_float4(fmaf(scale, l.x, -p.x), fmaf(scale, l.y, -p.y),
                           fmaf(scale, l.z, -p.z), fmaf(scale, l.w, -p.w));
    reinterpret_cast<float4*>(acc)[i] = s;
}

// Check-node update, two tiles per block. Both TMA fetches issue up front into
// independent buffers/mbarriers; tile B's fetch is hidden behind tile A's
// gather/min-sum/scatter work. No inter-tile __syncthreads needed.
__global__ void __launch_bounds__(CBLK) bp_check(const int* __restrict__ adj,
                                                 const float* __restrict__ gamma_p,
                                                 const float* __restrict__ src,
                                                 float* __restrict__ dst) {
    __shared__ __align__(16) int s_adj[2][TILE_INTS];
    __shared__ __align__(8) unsigned long long s_mbar[2];

    const int tid = threadIdx.x;
    const uint32_t mb0 = smem_u32(&s_mbar[0]);
    const uint32_t mb1 = smem_u32(&s_mbar[1]);

    if (tid == 0) { mbar_init(mb0, 1); mbar_init(mb1, 1); }
    __syncthreads();
    if (tid == 0) {
        const int* base = adj + (size_t)blockIdx.x * (2 * TILE_INTS);
        tma_1d(smem_u32(s_adj[0]), base, TILE_BYTES, mb0);
        tma_1d(smem_u32(s_adj[1]), base + TILE_INTS, TILE_BYTES, mb1);
    }

    // overlap scalar loads with the TMA fetches
    const float gamma = __ldg(gamma_p);
    const float vlast = __ldg(&src[N_VAR - 1]);  // all padded (-1) slots wrap here

    #pragma unroll
    for (int half = 0; half < 2; half++) {
        mbar_wait0(half == 0 ? mb0 : mb1);

        int idx[DC];
        #pragma unroll
        for (int j = 0; j < DC; j++) idx[j] = s_adj[half][tid * DC + j];

        float mag = __int_as_float(0x7f800000);  // +inf
        unsigned sgn = 0u;
        #pragma unroll
        for (int j = 0; j < DC; j++) {
            float v = (idx[j] >= 0) ? __ldcg(&src[idx[j]]) : vlast;
            sgn ^= (__float_as_uint(v + 1e-12f) & 0x80000000u);
            mag = fminf(mag, fabsf(v));
        }
        float c2v = __uint_as_float(__float_as_uint(gamma * mag) ^ sgn);

        #pragma unroll
        for (int j = 0; j < DC; j++) {
            if (idx[j] >= 0) atomicAdd(&dst[idx[j]], c2v);
        }
    }
}

extern "C" void kernel_launch(void* const* d_in, const int* in_sizes, int n_in,
                              void* d_out, int out_size) {
    const float* llr0  = (const float*)d_in[0];
    const float* gamma = (const float*)d_in[1];
    const int*   adj   = (const int*)d_in[2];
    float* out = (float*)d_out;

    float *b0, *b1, *b2;
    cudaGetSymbolAddress((void**)&b0, g_b0);
    cudaGetSymbolAddress((void**)&b1, g_b1);
    cudaGetSymbolAddress((void**)&b2, g_b2);

    const int seed_blocks = N_VAR / 4 / 512;   // 2048

    // n_iter = 5. Iter 1 is exact identity (v2c1 = llr0). Remaining 4 rounds:
    // accumulators pre-seeded with (llr0 - v2c_prev) so check's atomics produce
    // v2c_next in place; final accumulator is d_out seeded with (2*llr0 - v2c_4).
    cudaMemsetAsync(b0, 0, (size_t)N_VAR * sizeof(float));        // seed iter2: 0
    bp_check<<<NBLOCKS, CBLK>>>(adj, gamma, llr0, b0);            // b0 = v2c_2
    bp_seed<<<seed_blocks, 512>>>(llr0, b0, b1, 1.f);             // b1 = llr0 - v2c_2
    bp_check<<<NBLOCKS, CBLK>>>(adj, gamma, b0, b1);              // b1 = v2c_3
    bp_seed<<<seed_blocks, 512>>>(llr0, b1, b2, 1.f);             // b2 = llr0 - v2c_3
    bp_check<<<NBLOCKS, CBLK>>>(adj, gamma, b1, b2);              // b2 = v2c_4
    bp_seed<<<seed_blocks, 512>>>(llr0, b2, out, 2.f);            // out = 2*llr0 - v2c_4
    bp_check<<<NBLOCKS, CBLK>>>(adj, gamma, b2, out);             // out = llr0 + v2c_5
}

// round 10
// speedup vs baseline: 1.0337x; 1.0337x over previous
#include <cuda_runtime.h>
#include <cuda_bf16.h>
#include <cstdint>

#define N_VAR 4194304
#define M_CHK 2097152
#define DC 10
#define CBLK 256
#define ADJ_BYTES (CBLK * DC * 4)

// scratch (device globals: allocation-free)
__device__ float g_b0[N_VAR];
__device__ float g_b1[N_VAR];
__device__ float g_b2[N_VAR];

__device__ __forceinline__ uint32_t smem_u32(const void* p) {
    uint32_t a;
    asm("{ .reg .u64 t; cvta.to.shared.u64 t, %1; cvt.u32.u64 %0, t; }" : "=r"(a) : "l"(p));
    return a;
}

// seed accumulator: acc = scale*llr0 - v2c_prev  (scale = 1 mid, 2 for final/out)
// Single-wave config: 512 blocks x 512 threads, 4 float4 pairs each.
#define SEED_T 512
#define SEED_B 512
#define SEED_STRIDE (SEED_B * SEED_T)            // 262144
__global__ void __launch_bounds__(SEED_T) bp_seed(const float* __restrict__ llr0,
                                                  const float* __restrict__ v2c_prev,
                                                  float* __restrict__ acc, float scale) {
    int i = blockIdx.x * SEED_T + threadIdx.x;
    const float4* L = reinterpret_cast<const float4*>(llr0);
    const float4* P = reinterpret_cast<const float4*>(v2c_prev);
    float4* A = reinterpret_cast<float4*>(acc);

    float4 l[4], p[4];
    #pragma unroll
    for (int k = 0; k < 4; k++) l[k] = __ldcs(&L[i + k * SEED_STRIDE]);
    #pragma unroll
    for (int k = 0; k < 4; k++) p[k] = __ldcs(&P[i + k * SEED_STRIDE]);
    #pragma unroll
    for (int k = 0; k < 4; k++) {
        float4 s = make_float4(fmaf(scale, l[k].x, -p[k].x), fmaf(scale, l[k].y, -p[k].y),
                               fmaf(scale, l[k].z, -p[k].z), fmaf(scale, l[k].w, -p[k].w));
        A[i + k * SEED_STRIDE] = s;
    }
}

// check-node update: gather src (L2-only), min-sum, scatter-add into pre-seeded
// dst. adj rows staged to smem via TMA. Reference construction guarantees only
// adjacency slot DC-1 can be -1 (cn_adj.at[:, -1]); slots 0..8 are unconditional.
__global__ void __launch_bounds__(CBLK) bp_check(const int* __restrict__ adj,
                                                 const float* __restrict__ gamma_p,
                                                 const float* __restrict__ src,
                                                 float* __restrict__ dst) {
    __shared__ __align__(16) int s_adj[CBLK * DC];
    __shared__ __align__(8) unsigned long long s_mbar;

    const int tid = threadIdx.x;
    uint32_t mbar = smem_u32(&s_mbar);
    uint32_t sdst = smem_u32(s_adj);

    if (tid == 0) {
        asm volatile("mbarrier.init.shared.b64 [%0], 1;" :: "r"(mbar) : "memory");
    }
    __syncthreads();
    if (tid == 0) {
        asm volatile("mbarrier.arrive.expect_tx.shared.b64 _, [%0], %1;"
                     :: "r"(mbar), "r"((uint32_t)ADJ_BYTES) : "memory");
        const int* gsrc = adj + (size_t)blockIdx.x * (CBLK * DC);
        asm volatile(
            "cp.async.bulk.shared::cta.global.mbarrier::complete_tx::bytes "
            "[%0], [%1], %2, [%3];"
            :: "r"(sdst), "l"(gsrc), "r"((uint32_t)ADJ_BYTES), "r"(mbar) : "memory");
    }

    // overlap scalar loads with the TMA fetch
    const float gamma = __ldg(gamma_p);
    const float vlast = __ldg(&src[N_VAR - 1]);  // padded (-1) slot wraps here

    // wait for TMA completion (phase 0)
    {
        uint32_t done;
        asm volatile(
            "{\n\t.reg .pred p;\n\t"
            "mbarrier.try_wait.parity.acquire.cta.shared::cta.b64 p, [%1], 0;\n\t"
            "selp.b32 %0, 1, 0, p;\n\t}"
            : "=r"(done) : "r"(mbar) : "memory");
        while (!done) {
            asm volatile(
                "{\n\t.reg .pred p;\n\t"
                "mbarrier.try_wait.parity.acquire.cta.shared::cta.b64 p, [%1], 0, 0x989680;\n\t"
                "selp.b32 %0, 1, 0, p;\n\t}"
                : "=r"(done) : "r"(mbar) : "memory");
        }
    }

    int idx[DC];
    #pragma unroll
    for (int j = 0; j < DC; j++) idx[j] = s_adj[tid * DC + j];

    // slots 0..8: always valid -> unconditional gathers (front-batched, max MLP)
    float v[DC];
    #pragma unroll
    for (int j = 0; j < DC - 1; j++) v[j] = __ldcg(&src[idx[j]]);
    const bool last_valid = (idx[DC - 1] >= 0);
    v[DC - 1] = last_valid ? __ldcg(&src[idx[DC - 1]]) : vlast;

    float mag = __int_as_float(0x7f800000);  // +inf
    unsigned sgn = 0u;
    #pragma unroll
    for (int j = 0; j < DC; j++) {
        sgn ^= (__float_as_uint(v[j] + 1e-12f) & 0x80000000u);
        mag = fminf(mag, fabsf(v[j]));
    }
    float c2v = __uint_as_float(__float_as_uint(gamma * mag) ^ sgn);

    #pragma unroll
    for (int j = 0; j < DC - 1; j++) atomicAdd(&dst[idx[j]], c2v);
    if (last_valid) atomicAdd(&dst[idx[DC - 1]], c2v);
}

extern "C" void kernel_launch(void* const* d_in, const int* in_sizes, int n_in,
                              void* d_out, int out_size) {
    const float* llr0  = (const float*)d_in[0];
    const float* gamma = (const float*)d_in[1];
    const int*   adj   = (const int*)d_in[2];
    float* out = (float*)d_out;

    float *b0, *b1, *b2;
    cudaGetSymbolAddress((void**)&b0, g_b0);
    cudaGetSymbolAddress((void**)&b1, g_b1);
    cudaGetSymbolAddress((void**)&b2, g_b2);

    const int chk_blocks = M_CHK / CBLK;

    // n_iter = 5. Iter 1 is exact identity (v2c1 = llr0). Remaining 4 rounds:
    // accumulators pre-seeded with (llr0 - v2c_prev) so check's atomics produce
    // v2c_next in place; final accumulator is d_out seeded with (2*llr0 - v2c_4).
    cudaMemsetAsync(b0, 0, (size_t)N_VAR * sizeof(float));        // seed iter2: 0
    bp_check<<<chk_blocks, CBLK>>>(adj, gamma, llr0, b0);         // b0 = v2c_2
    bp_seed<<<SEED_B, SEED_T>>>(llr0, b0, b1, 1.f);               // b1 = llr0 - v2c_2
    bp_check<<<chk_blocks, CBLK>>>(adj, gamma, b0, b1);           // b1 = v2c_3
    bp_seed<<<SEED_B, SEED_T>>>(llr0, b1, b2, 1.f);               // b2 = llr0 - v2c_3
    bp_check<<<chk_blocks, CBLK>>>(adj, gamma, b1, b2);           // b2 = v2c_4
    bp_seed<<<SEED_B, SEED_T>>>(llr0, b2, out, 2.f);              // out = 2*llr0 - v2c_4
    bp_check<<<chk_blocks, CBLK>>>(adj, gamma, b2, out);          // out = llr0 + v2c_5
}

// round 11
// speedup vs baseline: 1.0420x; 1.0080x over previous
#include <cuda_runtime.h>
#include <cuda_bf16.h>
#include <cstdint>

#define N_VAR 4194304
#define M_CHK 2097152
#define DC 10
#define CBLK 256
#define ADJ_BYTES (CBLK * DC * 4)

// scratch (device globals: allocation-free)
__device__ float g_b0[N_VAR];
__device__ float g_b1[N_VAR];
__device__ float g_b2[N_VAR];

__device__ __forceinline__ uint32_t smem_u32(const void* p) {
    uint32_t a;
    asm("{ .reg .u64 t; cvta.to.shared.u64 t, %1; cvt.u32.u64 %0, t; }" : "=r"(a) : "l"(p));
    return a;
}

// seed accumulator: acc = scale*llr0 - v2c_prev  (scale = 1 mid, 2 for final/out)
// Best-measured config: 2048 blocks x 512 threads, 1 float4 per thread (9.3us).
__global__ void __launch_bounds__(512) bp_seed(const float* __restrict__ llr0,
                                               const float* __restrict__ v2c_prev,
                                               float* __restrict__ acc, float scale) {
    int i = blockIdx.x * 512 + threadIdx.x;
    float4 l = __ldg(&reinterpret_cast<const float4*>(llr0)[i]);
    float4 p = __ldg(&reinterpret_cast<const float4*>(v2c_prev)[i]);
    float4 s = make_float4(fmaf(scale, l.x, -p.x), fmaf(scale, l.y, -p.y),
                           fmaf(scale, l.z, -p.z), fmaf(scale, l.w, -p.w));
    reinterpret_cast<float4*>(acc)[i] = s;
}

// check-node update: gather src (L2-only), min-sum, scatter-add into pre-seeded
// dst. adj rows staged to smem via TMA (keeps L1tex wavefronts for gathers/REDs).
__global__ void __launch_bounds__(CBLK) bp_check(const int* __restrict__ adj,
                                                 const float* __restrict__ gamma_p,
                                                 const float* __restrict__ src,
                                                 float* __restrict__ dst) {
    __shared__ __align__(16) int s_adj[CBLK * DC];
    __shared__ __align__(8) unsigned long long s_mbar;

    const int tid = threadIdx.x;
    uint32_t mbar = smem_u32(&s_mbar);
    uint32_t sdst = smem_u32(s_adj);

    if (tid == 0) {
        asm volatile("mbarrier.init.shared.b64 [%0], 1;" :: "r"(mbar) : "memory");
    }
    __syncthreads();
    if (tid == 0) {
        asm volatile("mbarrier.arrive.expect_tx.shared.b64 _, [%0], %1;"
                     :: "r"(mbar), "r"((uint32_t)ADJ_BYTES) : "memory");
        const int* gsrc = adj + (size_t)blockIdx.x * (CBLK * DC);
        asm volatile(
            "cp.async.bulk.shared::cta.global.mbarrier::complete_tx::bytes "
            "[%0], [%1], %2, [%3];"
            :: "r"(sdst), "l"(gsrc), "r"((uint32_t)ADJ_BYTES), "r"(mbar) : "memory");
    }

    // overlap scalar loads with the TMA fetch
    const float gamma = __ldg(gamma_p);
    const float vlast = __ldg(&src[N_VAR - 1]);  // all padded (-1) slots wrap here

    // wait for TMA completion (phase 0)
    {
        uint32_t done;
        asm volatile(
            "{\n\t.reg .pred p;\n\t"
            "mbarrier.try_wait.parity.acquire.cta.shared::cta.b64 p, [%1], 0;\n\t"
            "selp.b32 %0, 1, 0, p;\n\t}"
            : "=r"(done) : "r"(mbar) : "memory");
        while (!done) {
            asm volatile(
                "{\n\t.reg .pred p;\n\t"
                "mbarrier.try_wait.parity.acquire.cta.shared::cta.b64 p, [%1], 0, 0x989680;\n\t"
                "selp.b32 %0, 1, 0, p;\n\t}"
                : "=r"(done) : "r"(mbar) : "memory");
        }
    }

    int idx[DC];
    #pragma unroll
    for (int j = 0; j < DC; j++) idx[j] = s_adj[tid * DC + j];

    float mag = __int_as_float(0x7f800000);  // +inf
    unsigned sgn = 0u;
    #pragma unroll
    for (int j = 0; j < DC; j++) {
        float v = (idx[j] >= 0) ? __ldcg(&src[idx[j]]) : vlast;
        sgn ^= (__float_as_uint(v + 1e-12f) & 0x80000000u);
        mag = fminf(mag, fabsf(v));
    }
    float c2v = __uint_as_float(__float_as_uint(gamma * mag) ^ sgn);

    #pragma unroll
    for (int j = 0; j < DC; j++) {
        if (idx[j] >= 0) atomicAdd(&dst[idx[j]], c2v);
    }
}

extern "C" void kernel_launch(void* const* d_in, const int* in_sizes, int n_in,
                              void* d_out, int out_size) {
    const float* llr0  = (const float*)d_in[0];
    const float* gamma = (const float*)d_in[1];
    const int*   adj   = (const int*)d_in[2];
    float* out = (float*)d_out;

    float *b0, *b1, *b2;
    cudaGetSymbolAddress((void**)&b0, g_b0);
    cudaGetSymbolAddress((void**)&b1, g_b1);
    cudaGetSymbolAddress((void**)&b2, g_b2);

    const int seed_blocks = N_VAR / 4 / 512;   // 2048
    const int chk_blocks = M_CHK / CBLK;

    // n_iter = 5. Iter 1 is exact identity (v2c1 = llr0). Remaining 4 rounds:
    // accumulators pre-seeded with (llr0 - v2c_prev) so check's atomics produce
    // v2c_next in place; final accumulator is d_out seeded with (2*llr0 - v2c_4).
    cudaMemsetAsync(b0, 0, (size_t)N_VAR * sizeof(float));        // seed iter2: 0
    bp_check<<<chk_blocks, CBLK>>>(adj, gamma, llr0, b0);         // b0 = v2c_2
    bp_seed<<<seed_blocks, 512>>>(llr0, b0, b1, 1.f);             // b1 = llr0 - v2c_2
    bp_check<<<chk_blocks, CBLK>>>(adj, gamma, b0, b1);           // b1 = v2c_3
    bp_seed<<<seed_blocks, 512>>>(llr0, b1, b2, 1.f);             // b2 = llr0 - v2c_3
    bp_check<<<chk_blocks, CBLK>>>(adj, gamma, b1, b2);           // b2 = v2c_4
    bp_seed<<<seed_blocks, 512>>>(llr0, b2, out, 2.f);            // out = 2*llr0 - v2c_4
    bp_check<<<chk_blocks, CBLK>>>(adj, gamma, b2, out);          // out = llr0 + v2c_5
}

// round 12
// speedup vs baseline: 1.0550x; 1.0125x over previous
#include <cuda_runtime.h>
#include <cuda_bf16.h>
#include <cstdint>

#define N_VAR 4194304
#define M_CHK 2097152
#define DC 10
#define CBLK 256
#define ADJ_BYTES (CBLK * DC * 4)

// scratch (device globals: allocation-free)
__device__ float g_b0[N_VAR];
__device__ float g_b1[N_VAR];
__device__ float g_b2[N_VAR];

__device__ __forceinline__ uint32_t smem_u32(const void* p) {
    uint32_t a;
    asm("{ .reg .u64 t; cvta.to.shared.u64 t, %1; cvt.u32.u64 %0, t; }" : "=r"(a) : "l"(p));
    return a;
}
__device__ __forceinline__ void pdl_trigger() {
    asm volatile("griddepcontrol.launch_dependents;");
}
__device__ __forceinline__ void pdl_wait() {
    asm volatile("griddepcontrol.wait;" ::: "memory");
}

// zero the first accumulator (kernel, not memset, so the PDL chain is unbroken)
__global__ void __launch_bounds__(512) bp_zero(float* __restrict__ acc) {
    pdl_trigger();
    int i = blockIdx.x * 512 + threadIdx.x;
    reinterpret_cast<float4*>(acc)[i] = make_float4(0.f, 0.f, 0.f, 0.f);
}

// seed accumulator: acc = scale*llr0 - v2c_prev  (scale = 1 mid, 2 for final/out)
__global__ void __launch_bounds__(512) bp_seed(const float* __restrict__ llr0,
                                               const float* __restrict__ v2c_prev,
                                               float* __restrict__ acc, float scale) {
    int i = blockIdx.x * 512 + threadIdx.x;
    pdl_trigger();
    pdl_wait();   // v2c_prev produced by the preceding check kernel
    float4 l = __ldg(&reinterpret_cast<const float4*>(llr0)[i]);
    float4 p = __ldg(&reinterpret_cast<const float4*>(v2c_prev)[i]);
    float4 s = make_float4(fmaf(scale, l.x, -p.x), fmaf(scale, l.y, -p.y),
                           fmaf(scale, l.z, -p.z), fmaf(scale, l.w, -p.w));
    reinterpret_cast<float4*>(acc)[i] = s;
}

// check-node update: gather src (L2-only), min-sum, scatter-add into pre-seeded
// dst. adj staged via TMA (input data — issued BEFORE pdl_wait so it overlaps
// the predecessor's tail); src/dst touched only after pdl_wait.
__global__ void __launch_bounds__(CBLK) bp_check(const int* __restrict__ adj,
                                                 const float* __restrict__ gamma_p,
                                                 const float* __restrict__ src,
                                                 float* __restrict__ dst) {
    __shared__ __align__(16) int s_adj[CBLK * DC];
    __shared__ __align__(8) unsigned long long s_mbar;

    const int tid = threadIdx.x;
    uint32_t mbar = smem_u32(&s_mbar);
    uint32_t sdst = smem_u32(s_adj);

    if (tid == 0) {
        asm volatile("mbarrier.init.shared.b64 [%0], 1;" :: "r"(mbar) : "memory");
    }
    __syncthreads();
    if (tid == 0) {
        asm volatile("mbarrier.arrive.expect_tx.shared.b64 _, [%0], %1;"
                     :: "r"(mbar), "r"((uint32_t)ADJ_BYTES) : "memory");
        const int* gsrc = adj + (size_t)blockIdx.x * (CBLK * DC);
        asm volatile(
            "cp.async.bulk.shared::cta.global.mbarrier::complete_tx::bytes "
            "[%0], [%1], %2, [%3];"
            :: "r"(sdst), "l"(gsrc), "r"((uint32_t)ADJ_BYTES), "r"(mbar) : "memory");
    }
    pdl_trigger();
    const float gamma = __ldg(gamma_p);   // kernel input, safe pre-wait

    pdl_wait();   // src and seeded dst produced by the predecessor
    const float vlast = __ldg(&src[N_VAR - 1]);  // all padded (-1) slots wrap here

    // wait for TMA completion (phase 0)
    {
        uint32_t done;
        asm volatile(
            "{\n\t.reg .pred p;\n\t"
            "mbarrier.try_wait.parity.acquire.cta.shared::cta.b64 p, [%1], 0;\n\t"
            "selp.b32 %0, 1, 0, p;\n\t}"
            : "=r"(done) : "r"(mbar) : "memory");
        while (!done) {
            asm volatile(
                "{\n\t.reg .pred p;\n\t"
                "mbarrier.try_wait.parity.acquire.cta.shared::cta.b64 p, [%1], 0, 0x989680;\n\t"
                "selp.b32 %0, 1, 0, p;\n\t}"
                : "=r"(done) : "r"(mbar) : "memory");
        }
    }

    int idx[DC];
    #pragma unroll
    for (int j = 0; j < DC; j++) idx[j] = s_adj[tid * DC + j];

    float mag = __int_as_float(0x7f800000);  // +inf
    unsigned sgn = 0u;
    #pragma unroll
    for (int j = 0; j < DC; j++) {
        float v = (idx[j] >= 0) ? __ldcg(&src[idx[j]]) : vlast;
        sgn ^= (__float_as_uint(v + 1e-12f) & 0x80000000u);
        mag = fminf(mag, fabsf(v));
    }
    float c2v = __uint_as_float(__float_as_uint(gamma * mag) ^ sgn);

    #pragma unroll
    for (int j = 0; j < DC; j++) {
        if (idx[j] >= 0) atomicAdd(&dst[idx[j]], c2v);
    }
}

template <typename... Args>
static void launch_pdl(void (*kern)(Args...), int grid, int block, Args... args) {
    cudaLaunchConfig_t cfg = {};
    cfg.gridDim = dim3(grid);
    cfg.blockDim = dim3(block);
    cfg.stream = 0;
    cudaLaunchAttribute attr[1];
    attr[0].id = cudaLaunchAttributeProgrammaticStreamSerialization;
    attr[0].val.programmaticStreamSerializationAllowed = 1;
    cfg.attrs = attr;
    cfg.numAttrs = 1;
    cudaLaunchKernelEx(&cfg, kern, args...);
}

extern "C" void kernel_launch(void* const* d_in, const int* in_sizes, int n_in,
                              void* d_out, int out_size) {
    const float* llr0  = (const float*)d_in[0];
    const float* gamma = (const float*)d_in[1];
    const int*   adj   = (const int*)d_in[2];
    float* out = (float*)d_out;

    float *b0, *b1, *b2;
    cudaGetSymbolAddress((void**)&b0, g_b0);
    cudaGetSymbolAddress((void**)&b1, g_b1);
    cudaGetSymbolAddress((void**)&b2, g_b2);

    const int seed_blocks = N_VAR / 4 / 512;   // 2048
    const int chk_blocks = M_CHK / CBLK;

    // n_iter = 5. Iter 1 is exact identity (v2c1 = llr0). Remaining 4 rounds:
    // accumulators pre-seeded with (llr0 - v2c_prev) so check's atomics produce
    // v2c_next in place; final accumulator is d_out seeded with (2*llr0 - v2c_4).
    // All launches use PDL so each kernel's prologue (TMA adj fetch, index math)
    // overlaps the predecessor's tail wave.
    launch_pdl(bp_zero, seed_blocks, 512, b0);                       // b0 = 0
    launch_pdl(bp_check, chk_blocks, CBLK, adj, gamma, llr0, b0);    // b0 = v2c_2
    launch_pdl(bp_seed, seed_blocks, 512, llr0, (const float*)b0, b1, 1.f); // b1 = llr0 - v2c_2
    launch_pdl(bp_check, chk_blocks, CBLK, adj, gamma, (const float*)b0, b1); // b1 = v2c_3
    launch_pdl(bp_seed, seed_blocks, 512, llr0, (const float*)b1, b2, 1.f); // b2 = llr0 - v2c_3
    launch_pdl(bp_check, chk_blocks, CBLK, adj, gamma, (const float*)b1, b2); // b2 = v2c_4
    launch_pdl(bp_seed, seed_blocks, 512, llr0, (const float*)b2, out, 2.f); // out = 2*llr0 - v2c_4
    launch_pdl(bp_check, chk_blocks, CBLK, adj, gamma, (const float*)b2, out); // out = llr0 + v2c_5
}

// round 13
// speedup vs baseline: 1.0558x; 1.0007x over previous
#include <cuda_runtime.h>
#include <cuda_bf16.h>
#include <cstdint>

#define N_VAR 4194304
#define M_CHK 2097152
#define DC 10
#define CBLK 256
#define ADJ_BYTES (CBLK * DC * 4)

// scratch (device globals: allocation-free)
__device__ float g_b0[N_VAR];
__device__ float g_b1[N_VAR];
__device__ float g_b2[N_VAR];

__device__ __forceinline__ uint32_t smem_u32(const void* p) {
    uint32_t a;
    asm("{ .reg .u64 t; cvta.to.shared.u64 t, %1; cvt.u32.u64 %0, t; }" : "=r"(a) : "l"(p));
    return a;
}
__device__ __forceinline__ void pdl_trigger() {
    asm volatile("griddepcontrol.launch_dependents;");
}
__device__ __forceinline__ void pdl_wait() {
    asm volatile("griddepcontrol.wait;" ::: "memory");
}

// zero the first accumulator (kernel, not memset, so the PDL chain is unbroken)
__global__ void __launch_bounds__(512) bp_zero(float* __restrict__ acc) {
    pdl_trigger();
    int i = blockIdx.x * 512 + threadIdx.x;
    reinterpret_cast<float4*>(acc)[i] = make_float4(0.f, 0.f, 0.f, 0.f);
}

// seed accumulator: acc = scale*llr0 - v2c_prev  (scale = 1 mid, 2 for final/out)
__global__ void __launch_bounds__(512) bp_seed(const float* __restrict__ llr0,
                                               const float* __restrict__ v2c_prev,
                                               float* __restrict__ acc, float scale) {
    int i = blockIdx.x * 512 + threadIdx.x;
    pdl_trigger();
    pdl_wait();   // v2c_prev produced by the preceding check kernel
    float4 l = __ldg(&reinterpret_cast<const float4*>(llr0)[i]);
    float4 p = __ldg(&reinterpret_cast<const float4*>(v2c_prev)[i]);
    float4 s = make_float4(fmaf(scale, l.x, -p.x), fmaf(scale, l.y, -p.y),
                           fmaf(scale, l.z, -p.z), fmaf(scale, l.w, -p.w));
    reinterpret_cast<float4*>(acc)[i] = s;
}

// check-node update: gather src (L2-only), min-sum, scatter-add into pre-seeded
// dst. Entire prologue (mbarrier init, TMA adj fetch + wait, smem index loads)
// runs BEFORE pdl_wait — it depends only on kernel inputs — so it overlaps the
// predecessor's tail wave. Only the src gathers / dst atomics are gated.
__global__ void __launch_bounds__(CBLK) bp_check(const int* __restrict__ adj,
                                                 const float* __restrict__ gamma_p,
                                                 const float* __restrict__ src,
                                                 float* __restrict__ dst) {
    __shared__ __align__(16) int s_adj[CBLK * DC];
    __shared__ __align__(8) unsigned long long s_mbar;

    const int tid = threadIdx.x;
    uint32_t mbar = smem_u32(&s_mbar);
    uint32_t sdst = smem_u32(s_adj);

    if (tid == 0) {
        asm volatile("mbarrier.init.shared.b64 [%0], 1;" :: "r"(mbar) : "memory");
    }
    __syncthreads();
    if (tid == 0) {
        asm volatile("mbarrier.arrive.expect_tx.shared.b64 _, [%0], %1;"
                     :: "r"(mbar), "r"((uint32_t)ADJ_BYTES) : "memory");
        const int* gsrc = adj + (size_t)blockIdx.x * (CBLK * DC);
        asm volatile(
            "cp.async.bulk.shared::cta.global.mbarrier::complete_tx::bytes "
            "[%0], [%1], %2, [%3];"
            :: "r"(sdst), "l"(gsrc), "r"((uint32_t)ADJ_BYTES), "r"(mbar) : "memory");
    }
    pdl_trigger();
    const float gamma = __ldg(gamma_p);   // kernel input, safe pre-wait

    // wait for TMA completion (phase 0) — input-only dependency, pre-wait
    {
        uint32_t done;
        asm volatile(
            "{\n\t.reg .pred p;\n\t"
            "mbarrier.try_wait.parity.acquire.cta.shared::cta.b64 p, [%1], 0;\n\t"
            "selp.b32 %0, 1, 0, p;\n\t}"
            : "=r"(done) : "r"(mbar) : "memory");
        while (!done) {
            asm volatile(
                "{\n\t.reg .pred p;\n\t"
                "mbarrier.try_wait.parity.acquire.cta.shared::cta.b64 p, [%1], 0, 0x989680;\n\t"
                "selp.b32 %0, 1, 0, p;\n\t}"
                : "=r"(done) : "r"(mbar) : "memory");
        }
    }

    int idx[DC];
    #pragma unroll
    for (int j = 0; j < DC; j++) idx[j] = s_adj[tid * DC + j];

    pdl_wait();   // src and seeded dst produced by the predecessor
    const float vlast = __ldg(&src[N_VAR - 1]);  // all padded (-1) slots wrap here

    float mag = __int_as_float(0x7f800000);  // +inf
    unsigned sgn = 0u;
    #pragma unroll
    for (int j = 0; j < DC; j++) {
        float v = (idx[j] >= 0) ? __ldcg(&src[idx[j]]) : vlast;
        sgn ^= (__float_as_uint(v + 1e-12f) & 0x80000000u);
        mag = fminf(mag, fabsf(v));
    }
    float c2v = __uint_as_float(__float_as_uint(gamma * mag) ^ sgn);

    #pragma unroll
    for (int j = 0; j < DC; j++) {
        if (idx[j] >= 0) atomicAdd(&dst[idx[j]], c2v);
    }
}

template <typename... Args>
static void launch_pdl(void (*kern)(Args...), int grid, int block, Args... args) {
    cudaLaunchConfig_t cfg = {};
    cfg.gridDim = dim3(grid);
    cfg.blockDim = dim3(block);
    cfg.stream = 0;
    cudaLaunchAttribute attr[1];
    attr[0].id = cudaLaunchAttributeProgrammaticStreamSerialization;
    attr[0].val.programmaticStreamSerializationAllowed = 1;
    cfg.attrs = attr;
    cfg.numAttrs = 1;
    cudaLaunchKernelEx(&cfg, kern, args...);
}

extern "C" void kernel_launch(void* const* d_in, const int* in_sizes, int n_in,
                              void* d_out, int out_size) {
    const float* llr0  = (const float*)d_in[0];
    const float* gamma = (const float*)d_in[1];
    const int*   adj   = (const int*)d_in[2];
    float* out = (float*)d_out;

    float *b0, *b1, *b2;
    cudaGetSymbolAddress((void**)&b0, g_b0);
    cudaGetSymbolAddress((void**)&b1, g_b1);
    cudaGetSymbolAddress((void**)&b2, g_b2);

    const int seed_blocks = N_VAR / 4 / 512;   // 2048
    const int chk_blocks = M_CHK / CBLK;

    // n_iter = 5. Iter 1 is exact identity (v2c1 = llr0). Remaining 4 rounds:
    // accumulators pre-seeded with (llr0 - v2c_prev) so check's atomics produce
    // v2c_next in place; final accumulator is d_out seeded with (2*llr0 - v2c_4).
    // All launches use PDL; each kernel's full input-only prologue overlaps the
    // predecessor's tail wave.
    launch_pdl(bp_zero, seed_blocks, 512, b0);                       // b0 = 0
    launch_pdl(bp_check, chk_blocks, CBLK, adj, gamma, llr0, b0);    // b0 = v2c_2
    launch_pdl(bp_seed, seed_blocks, 512, llr0, (const float*)b0, b1, 1.f); // b1 = llr0 - v2c_2
    launch_pdl(bp_check, chk_blocks, CBLK, adj, gamma, (const float*)b0, b1); // b1 = v2c_3
    launch_pdl(bp_seed, seed_blocks, 512, llr0, (const float*)b1, b2, 1.f); // b2 = llr0 - v2c_3
    launch_pdl(bp_check, chk_blocks, CBLK, adj, gamma, (const float*)b1, b2); // b2 = v2c_4
    launch_pdl(bp_seed, seed_blocks, 512, llr0, (const float*)b2, out, 2.f); // out = 2*llr0 - v2c_4
    launch_pdl(bp_check, chk_blocks, CBLK, adj, gamma, (const float*)b2, out); // out = llr0 + v2c_5
}

// round 14
// speedup vs baseline: 1.0693x; 1.0128x over previous
#include <cuda_runtime.h>
#include <cuda_bf16.h>
#include <cstdint>

#define N_VAR 4194304
#define M_CHK 2097152
#define DC 10
#define CBLK 128
#define ADJ_BYTES (CBLK * DC * 4)

// scratch (device globals: allocation-free)
__device__ float g_b0[N_VAR];
__device__ float g_b1[N_VAR];
__device__ float g_b2[N_VAR];

__device__ __forceinline__ uint32_t smem_u32(const void* p) {
    uint32_t a;
    asm("{ .reg .u64 t; cvta.to.shared.u64 t, %1; cvt.u32.u64 %0, t; }" : "=r"(a) : "l"(p));
    return a;
}
__device__ __forceinline__ void pdl_trigger() {
    asm volatile("griddepcontrol.launch_dependents;");
}
__device__ __forceinline__ void pdl_wait() {
    asm volatile("griddepcontrol.wait;" ::: "memory");
}

// zero the first accumulator (kernel, not memset, so the PDL chain is unbroken)
__global__ void __launch_bounds__(512) bp_zero(float* __restrict__ acc) {
    pdl_trigger();
    int i = blockIdx.x * 512 + threadIdx.x;
    reinterpret_cast<float4*>(acc)[i] = make_float4(0.f, 0.f, 0.f, 0.f);
}

// seed accumulator: acc = scale*llr0 - v2c_prev  (scale = 1 mid, 2 for final/out)
__global__ void __launch_bounds__(512) bp_seed(const float* __restrict__ llr0,
                                               const float* __restrict__ v2c_prev,
                                               float* __restrict__ acc, float scale) {
    int i = blockIdx.x * 512 + threadIdx.x;
    pdl_trigger();
    pdl_wait();   // v2c_prev produced by the preceding check kernel
    float4 l = __ldg(&reinterpret_cast<const float4*>(llr0)[i]);
    float4 p = __ldg(&reinterpret_cast<const float4*>(v2c_prev)[i]);
    float4 s = make_float4(fmaf(scale, l.x, -p.x), fmaf(scale, l.y, -p.y),
                           fmaf(scale, l.z, -p.z), fmaf(scale, l.w, -p.w));
    reinterpret_cast<float4*>(acc)[i] = s;
}

// check-node update: gather src (L2-only), min-sum, scatter-add into pre-seeded
// dst. Entire prologue (mbarrier init, TMA adj fetch + wait, smem index loads)
// runs BEFORE pdl_wait; only the src gathers / dst atomics are gated.
__global__ void __launch_bounds__(CBLK) bp_check(const int* __restrict__ adj,
                                                 const float* __restrict__ gamma_p,
                                                 const float* __restrict__ src,
                                                 float* __restrict__ dst) {
    __shared__ __align__(16) int s_adj[CBLK * DC];
    __shared__ __align__(8) unsigned long long s_mbar;

    const int tid = threadIdx.x;
    uint32_t mbar = smem_u32(&s_mbar);
    uint32_t sdst = smem_u32(s_adj);

    if (tid == 0) {
        asm volatile("mbarrier.init.shared.b64 [%0], 1;" :: "r"(mbar) : "memory");
    }
    __syncthreads();
    if (tid == 0) {
        asm volatile("mbarrier.arrive.expect_tx.shared.b64 _, [%0], %1;"
                     :: "r"(mbar), "r"((uint32_t)ADJ_BYTES) : "memory");
        const int* gsrc = adj + (size_t)blockIdx.x * (CBLK * DC);
        asm volatile(
            "cp.async.bulk.shared::cta.global.mbarrier::complete_tx::bytes "
            "[%0], [%1], %2, [%3];"
            :: "r"(sdst), "l"(gsrc), "r"((uint32_t)ADJ_BYTES), "r"(mbar) : "memory");
    }
    pdl_trigger();
    const float gamma = __ldg(gamma_p);   // kernel input, safe pre-wait

    // wait for TMA completion (phase 0) — input-only dependency, pre-wait
    {
        uint32_t done;
        asm volatile(
            "{\n\t.reg .pred p;\n\t"
            "mbarrier.try_wait.parity.acquire.cta.shared::cta.b64 p, [%1], 0;\n\t"
            "selp.b32 %0, 1, 0, p;\n\t}"
            : "=r"(done) : "r"(mbar) : "memory");
        while (!done) {
            asm volatile(
                "{\n\t.reg .pred p;\n\t"
                "mbarrier.try_wait.parity.acquire.cta.shared::cta.b64 p, [%1], 0, 0x989680;\n\t"
                "selp.b32 %0, 1, 0, p;\n\t}"
                : "=r"(done) : "r"(mbar) : "memory");
        }
    }

    int idx[DC];
    #pragma unroll
    for (int j = 0; j < DC; j++) idx[j] = s_adj[tid * DC + j];

    pdl_wait();   // src and seeded dst produced by the predecessor
    const float vlast = __ldg(&src[N_VAR - 1]);  // all padded (-1) slots wrap here

    float mag = __int_as_float(0x7f800000);  // +inf
    unsigned sgn = 0u;
    #pragma unroll
    for (int j = 0; j < DC; j++) {
        float v = (idx[j] >= 0) ? __ldcg(&src[idx[j]]) : vlast;
        sgn ^= (__float_as_uint(v + 1e-12f) & 0x80000000u);
        mag = fminf(mag, fabsf(v));
    }
    float c2v = __uint_as_float(__float_as_uint(gamma * mag) ^ sgn);

    #pragma unroll
    for (int j = 0; j < DC; j++) {
        if (idx[j] >= 0) atomicAdd(&dst[idx[j]], c2v);
    }
}

template <typename... Args>
static void launch_pdl(void (*kern)(Args...), int grid, int block, Args... args) {
    cudaLaunchConfig_t cfg = {};
    cfg.gridDim = dim3(grid);
    cfg.blockDim = dim3(block);
    cfg.stream = 0;
    cudaLaunchAttribute attr[1];
    attr[0].id = cudaLaunchAttributeProgrammaticStreamSerialization;
    attr[0].val.programmaticStreamSerializationAllowed = 1;
    cfg.attrs = attr;
    cfg.numAttrs = 1;
    cudaLaunchKernelEx(&cfg, kern, args...);
}

extern "C" void kernel_launch(void* const* d_in, const int* in_sizes, int n_in,
                              void* d_out, int out_size) {
    const float* llr0  = (const float*)d_in[0];
    const float* gamma = (const float*)d_in[1];
    const int*   adj   = (const int*)d_in[2];
    float* out = (float*)d_out;

    float *b0, *b1, *b2;
    cudaGetSymbolAddress((void**)&b0, g_b0);
    cudaGetSymbolAddress((void**)&b1, g_b1);
    cudaGetSymbolAddress((void**)&b2, g_b2);

    const int seed_blocks = N_VAR / 4 / 512;   // 2048
    const int chk_blocks = M_CHK / CBLK;       // 16384

    // n_iter = 5. Iter 1 is exact identity (v2c1 = llr0). Remaining 4 rounds:
    // accumulators pre-seeded with (llr0 - v2c_prev) so check's atomics produce
    // v2c_next in place; final accumulator is d_out seeded with (2*llr0 - v2c_4).
    // All launches use PDL; each kernel's input-only prologue overlaps the
    // predecessor's tail wave.
    launch_pdl(bp_zero, seed_blocks, 512, b0);                       // b0 = 0
    launch_pdl(bp_check, chk_blocks, CBLK, adj, gamma, llr0, b0);    // b0 = v2c_2
    launch_pdl(bp_seed, seed_blocks, 512, llr0, (const float*)b0, b1, 1.f); // b1 = llr0 - v2c_2
    launch_pdl(bp_check, chk_blocks, CBLK, adj, gamma, (const float*)b0, b1); // b1 = v2c_3
    launch_pdl(bp_seed, seed_blocks, 512, llr0, (const float*)b1, b2, 1.f); // b2 = llr0 - v2c_3
    launch_pdl(bp_check, chk_blocks, CBLK, adj, gamma, (const float*)b1, b2); // b2 = v2c_4
    launch_pdl(bp_seed, seed_blocks, 512, llr0, (const float*)b2, out, 2.f); // out = 2*llr0 - v2c_4
    launch_pdl(bp_check, chk_blocks, CBLK, adj, gamma, (const float*)b2, out); // out = llr0 + v2c_5
}